// round 8
// baseline (speedup 1.0000x reference)
#include <cuda_runtime.h>
#include <cstdint>
#include <math.h>

// ---------------------------------------------------------------------------
//   x: [4,16,64,64,64] f32    weights1/2: [2,4] f32    out: [4,32,32,32,32] f32
// <Z0> = v^T S v  ->  81 coeffs in double-angle basis (1, cos2a, sin2a),
// 2a = min(pi, pi*y). Each thread evaluates 2 adjacent l-points (shared W LDS).
// Single kernel: W rebuilt in-block via warp-shuffle simulator.
// ---------------------------------------------------------------------------

#define MAXOPS 64

struct Plan {
    int n;
    int type[MAXOPS];   // 0=RX, 1=RY, 2=RZ, 3=CNOT
    int a[MAXOPS];      // rot wire, or cnot control
    int b[MAXOPS];      // cnot target
    int widx[MAXOPS];   // weights flat index l*4+i
};

// ---------------------------------------------------------------------------
// grid = 640 blocks x 256 threads:
//   [0,512):   compute. blk = bc*8 + jg;  thread = slice(1b) k(4b) lq(3b)
//              j = 2*jg+slice, each thread does points (k, 2lq) and (k, 2lq+1)
//   [512,640): zero-fill of the j>=16 half (one (b,ch) 64KB chunk per block)
// ---------------------------------------------------------------------------
__global__ void __launch_bounds__(256)
qconv_one_kernel(const float* __restrict__ x,
                 const float* __restrict__ w1,
                 const float* __restrict__ w2,
                 float* __restrict__ out, Plan plan) {
    int t = threadIdx.x;

    if (blockIdx.x >= 512) {
        int zi = blockIdx.x - 512;           // 0..127 -> (b, ch)
        float4* dst = reinterpret_cast<float4*>(
            out + (size_t)(zi >> 5) * 1048576 + (size_t)(zi & 31) * 32768 + 16384);
        const float4 z4 = make_float4(0.f, 0.f, 0.f, 0.f);
        #pragma unroll
        for (int r = 0; r < 16; r++) dst[t + 256 * r] = z4;
        return;
    }

    __shared__ float Ur[16][16], Ui[16][16];
    __shared__ float Wsh[2][81];
    __shared__ float WB[81];
    __shared__ __align__(16) float tile[2][2][16][16];   // [set][slice][k][l]

    int bc    = blockIdx.x >> 3;   // b*16 + c
    int jg    = blockIdx.x & 7;
    int slice = t >> 7;            // 0..1
    int k     = (t >> 3) & 15;
    int lq    = t & 7;
    int j     = 2 * jg + slice;

    // ---- global loads first: latency hides under the W build ----
    const float* xb = x + (size_t)bc * 262144 + (size_t)(2 * j) * 4096
                        + (size_t)(2 * k) * 64 + 4 * lq;
    float4 v00 = *reinterpret_cast<const float4*>(xb);
    float4 v01 = *reinterpret_cast<const float4*>(xb + 64);
    float4 v10 = *reinterpret_cast<const float4*>(xb + 4096);
    float4 v11 = *reinterpret_cast<const float4*>(xb + 4096 + 64);

    // ---- in-block W build, both weight sets (shuffle simulator, verified) ----
    {
        int col = t >> 4, amp = t & 15, lane = t & 31;
        for (int ws = 0; ws < 2; ws++) {
            const float* w = ws ? w2 : w1;
            float sr = (amp == col) ? 1.f : 0.f;
            float si = 0.f;
            for (int o = 0; o < plan.n; o++) {
                int ty = plan.type[o];
                if (ty == 3) {
                    int bcb = 3 - plan.a[o], btb = 3 - plan.b[o];
                    int src_amp  = amp ^ ((((amp >> bcb) & 1) ? 1 : 0) << btb);
                    int src_lane = (lane & 16) | src_amp;
                    sr = __shfl_sync(0xFFFFFFFFu, sr, src_lane);
                    si = __shfl_sync(0xFFFFFFFFu, si, src_lane);
                } else {
                    float th = w[plan.widx[o]];
                    float c = cosf(0.5f * th), s = sinf(0.5f * th);
                    float a00r = c, a00i = 0.f, a01r = 0.f, a01i = 0.f;
                    float a10r = 0.f, a10i = 0.f, a11r = c, a11i = 0.f;
                    if (ty == 0)      { a01i = -s; a10i = -s; }      // RX
                    else if (ty == 1) { a01r = -s; a10r =  s; }      // RY
                    else              { a00i = -s; a11i =  s; }      // RZ
                    int bitp = 3 - plan.a[o];
                    int str  = 1 << bitp;
                    float pr = __shfl_xor_sync(0xFFFFFFFFu, sr, str);
                    float pi = __shfl_xor_sync(0xFFFFFFFFu, si, str);
                    int bit = (amp >> bitp) & 1;
                    float xr = bit ? pr : sr, xi = bit ? pi : si;
                    float yr = bit ? sr : pr, yi = bit ? si : pi;
                    float r0r = bit ? a10r : a00r, r0i = bit ? a10i : a00i;
                    float r1r = bit ? a11r : a01r, r1i = bit ? a11i : a01i;
                    sr = r0r * xr - r0i * xi + r1r * yr - r1i * yi;
                    si = r0r * xi + r0i * xr + r1r * yi + r1i * yr;
                }
            }
            Ur[amp][col] = sr;
            Ui[amp][col] = si;
            if (t < 81) Wsh[ws][t] = 0.f;
            __syncthreads();

            {   // S[r][c] binned into 81 monomials via shared atomics
                int r = t >> 4, c = t & 15;
                float acc = 0.f;
                #pragma unroll
                for (int kk = 0; kk < 16; kk++) {
                    float z = (kk & 8) ? -1.f : 1.f;
                    acc += z * (Ur[kk][r] * Ur[kk][c] + Ui[kk][r] * Ui[kk][c]);
                }
                int m0 = ((r >> 3) & 1) + ((c >> 3) & 1);
                int m1 = ((r >> 2) & 1) + ((c >> 2) & 1);
                int m2 = ((r >> 1) & 1) + ((c >> 1) & 1);
                int m3 = (r & 1) + (c & 1);
                atomicAdd(&Wsh[ws][((m0 * 3 + m1) * 3 + m2) * 3 + m3], acc);
            }

            // basis change [c^2,cs,s^2] -> [1,cos2a,sin2a], 4 strided passes
            #define XFORM(SRC, DST, S)                                        \
                __syncthreads();                                              \
                if (t < 81) {                                                 \
                    int n = (t / (S)) % 3;                                    \
                    int base = t - n * (S);                                   \
                    float i0 = SRC[base], i1 = SRC[base + (S)],               \
                          i2 = SRC[base + 2 * (S)];                           \
                    DST[t] = (n == 0) ? 0.5f * (i0 + i2)                      \
                           : (n == 1) ? 0.5f * (i0 - i2) : 0.5f * i1;         \
                }
            XFORM(Wsh[ws], WB, 27)
            XFORM(WB, Wsh[ws], 9)
            XFORM(Wsh[ws], WB, 3)
            XFORM(WB, Wsh[ws], 1)
            #undef XFORM
        }
    }

    // ---- per-point trig: CC/SS[p][dj][dk][dl], p = l parity ----
    const float PI_F = 3.14159265358979323846f;
    float CC[2][2][2][2], SS[2][2][2][2];
    {
        const float4* vv[2][2] = { { &v00, &v01 }, { &v10, &v11 } };
        #pragma unroll
        for (int dj = 0; dj < 2; dj++)
            #pragma unroll
            for (int dk = 0; dk < 2; dk++) {
                float4 v = *vv[dj][dk];
                float g[2][2] = { { v.x, v.y }, { v.z, v.w } };  // [p][dl]
                #pragma unroll
                for (int p = 0; p < 2; p++)
                    #pragma unroll
                    for (int dl = 0; dl < 2; dl++) {
                        float th2 = fminf(PI_F, PI_F * g[p][dl]);
                        __sincosf(th2, &SS[p][dj][dk][dl], &CC[p][dj][dk][dl]);
                    }
            }
    }

    __syncthreads();   // Wsh ready

    // monomial row: M = {1, Cb, Sb, Ca, CaCb, CaSb, Sa, SaCb, SaSb}
    #define MONO(M, Ca, Sa, Cb, Sb)                                           \
        { M[0] = 1.f;  M[1] = (Cb); M[2] = (Sb);                              \
          M[3] = (Ca); M[4] = (Ca) * (Cb); M[5] = (Ca) * (Sb);                \
          M[6] = (Sa); M[7] = (Sa) * (Cb); M[8] = (Sa) * (Sb); }

    float e[2][2];   // [set][p]
    #pragma unroll
    for (int s = 0; s < 2; s++) {
        float M01[2][9], M23[2][9];
        #pragma unroll
        for (int p = 0; p < 2; p++) {
            if (s == 0) {
                // circuit 1: q = g(0,0,0), g(1,1,0), g(0,1,1), g(1,0,1)
                MONO(M01[p], CC[p][0][0][0], SS[p][0][0][0],
                             CC[p][1][1][0], SS[p][1][1][0]);
                MONO(M23[p], CC[p][0][1][1], SS[p][0][1][1],
                             CC[p][1][0][1], SS[p][1][0][1]);
            } else {
                // circuit 2: q = g(1,1,1), g(0,0,1), g(1,0,0), g(0,1,0)
                MONO(M01[p], CC[p][1][1][1], SS[p][1][1][1],
                             CC[p][0][0][1], SS[p][0][0][1]);
                MONO(M23[p], CC[p][1][0][0], SS[p][1][0][0],
                             CC[p][0][1][0], SS[p][0][1][0]);
            }
        }
        float e0 = 0.f, e1 = 0.f;
        #pragma unroll
        for (int a = 0; a < 9; a++) {
            float t0 = 0.f, t1 = 0.f;
            #pragma unroll
            for (int b = 0; b < 9; b++) {
                float wv = Wsh[s][a * 9 + b];      // one LDS serves 2 points
                t0 = fmaf(wv, M23[0][b], t0);
                t1 = fmaf(wv, M23[1][b], t1);
            }
            e0 = fmaf(M01[0][a], t0, e0);
            e1 = fmaf(M01[1][a], t1, e1);
        }
        e[s][0] = e0;
        e[s][1] = e1;
    }
    #undef MONO

    tile[0][slice][k][2 * lq]     = e[0][0];
    tile[0][slice][k][2 * lq + 1] = e[0][1];
    tile[1][slice][k][2 * lq]     = e[1][0];
    tile[1][slice][k][2 * lq + 1] = e[1][1];
    __syncthreads();

    // ---- epilogue: 4 output slices (2 sets x 2 j), zero-padded to 32x32 ----
    int b  = bc >> 4, c = bc & 15;
    int k2 = t >> 3;   // 0..31
    int q  = t & 7;    // float4 quad
    const float4 z4 = make_float4(0.f, 0.f, 0.f, 0.f);
    #pragma unroll
    for (int s = 0; s < 2; s++)
        #pragma unroll
        for (int js = 0; js < 2; js++) {
            float4 v = (k2 < 16 && q < 4)
                     ? reinterpret_cast<const float4*>(tile[s][js][k2])[q] : z4;
            float4* dst = reinterpret_cast<float4*>(
                out + (size_t)b * 1048576 + (size_t)(c + 16 * s) * 32768
                    + (size_t)(2 * jg + js) * 1024);
            dst[t] = v;
        }
}

// ---------------------------------------------------------------------------
// Host: exact numpy default_rng(1234) plan generation (verified R3).
// ---------------------------------------------------------------------------
typedef unsigned __int128 u128;

struct NpRng {
    u128 state, inc;
    bool has32;
    uint32_t buf32;

    static u128 mult() {
        return ((u128)2549297995355413924ULL << 64) | 4865540595714422341ULL;
    }
    uint64_t next64() {
        state = state * mult() + inc;
        uint64_t hi = (uint64_t)(state >> 64);
        uint64_t lo = (uint64_t)state;
        unsigned rot = (unsigned)(state >> 122);
        uint64_t v = hi ^ lo;
        return (v >> rot) | (v << ((64u - rot) & 63u));
    }
    uint32_t next32() {
        if (has32) { has32 = false; return buf32; }
        uint64_t n = next64();
        has32 = true;
        buf32 = (uint32_t)(n >> 32);
        return (uint32_t)n;
    }
    double nextDouble() {
        return (double)(next64() >> 11) * (1.0 / 9007199254740992.0);
    }
    uint32_t lemire32(uint32_t rng) {
        uint32_t rng_excl = rng + 1u;
        uint64_t m = (uint64_t)next32() * (uint64_t)rng_excl;
        uint32_t leftover = (uint32_t)m;
        if (leftover < rng_excl) {
            uint32_t threshold = (uint32_t)((0xFFFFFFFFu - rng) % rng_excl);
            while (leftover < threshold) {
                m = (uint64_t)next32() * (uint64_t)rng_excl;
                leftover = (uint32_t)m;
            }
        }
        return (uint32_t)(m >> 32);
    }
};

static Plan make_plan_host() {
    const uint32_t INIT_A = 0x43b0d7e5u, MULT_A = 0x931e8875u;
    const uint32_t INIT_B = 0x8b51f9ddu, MULT_B = 0x58f38dedu;
    const uint32_t MIX_L  = 0xca01f9ddu, MIX_R  = 0x4973f715u;

    uint32_t pool[4];
    uint32_t hc = INIT_A;
    auto hashmix = [&](uint32_t v) -> uint32_t {
        v ^= hc; hc *= MULT_A; v *= hc; v ^= v >> 16; return v;
    };
    auto mixf = [&](uint32_t x, uint32_t y) -> uint32_t {
        uint32_t r = x * MIX_L - y * MIX_R; r ^= r >> 16; return r;
    };
    pool[0] = hashmix(1234u);
    pool[1] = hashmix(0u);
    pool[2] = hashmix(0u);
    pool[3] = hashmix(0u);
    for (int s = 0; s < 4; s++)
        for (int d = 0; d < 4; d++)
            if (s != d) pool[d] = mixf(pool[d], hashmix(pool[s]));

    uint32_t hb = INIT_B;
    uint32_t st32[8];
    for (int i = 0; i < 8; i++) {
        uint32_t dv = pool[i & 3];
        dv ^= hb; hb *= MULT_B; dv *= hb; dv ^= dv >> 16;
        st32[i] = dv;
    }
    uint64_t s64[4];
    for (int i = 0; i < 4; i++)
        s64[i] = (uint64_t)st32[2 * i] | ((uint64_t)st32[2 * i + 1] << 32);

    NpRng rng;
    u128 initstate = ((u128)s64[0] << 64) | s64[1];
    u128 initseq   = ((u128)s64[2] << 64) | s64[3];
    rng.inc   = (initseq << 1) | 1;
    rng.state = 0;
    rng.state = rng.state * NpRng::mult() + rng.inc;
    rng.state += initstate;
    rng.state = rng.state * NpRng::mult() + rng.inc;
    rng.has32 = false;
    rng.buf32 = 0;

    Plan plan;
    plan.n = 0;
    for (int l = 0; l < 2; l++) {
        int i = 0;
        while (i < 4 && plan.n < MAXOPS) {
            if (rng.nextDouble() > 0.3) {
                int g = (int)rng.lemire32(2);
                int w = (int)rng.lemire32(3);
                plan.type[plan.n] = g;
                plan.a[plan.n]    = w;
                plan.b[plan.n]    = 0;
                plan.widx[plan.n] = l * 4 + i;
                plan.n++;
                i++;
            } else {
                uint64_t hash_set[4] = { ~0ULL, ~0ULL, ~0ULL, ~0ULL };
                int64_t idx[2];
                for (int jf = 2; jf <= 3; jf++) {
                    uint64_t val = (uint64_t)rng.lemire32((uint32_t)jf);
                    uint64_t loc = val & 3;
                    while (hash_set[loc] != ~0ULL && hash_set[loc] != val)
                        loc = (loc + 1) & 3;
                    if (hash_set[loc] == ~0ULL) {
                        hash_set[loc] = val;
                        idx[jf - 2] = (int64_t)val;
                    } else {
                        loc = (uint64_t)jf & 3;
                        while (hash_set[loc] != ~0ULL) loc = (loc + 1) & 3;
                        hash_set[loc] = (uint64_t)jf;
                        idx[jf - 2] = jf;
                    }
                }
                uint32_t sh = rng.lemire32(1u);   // Lemire-32 (top bit)
                int64_t tmp = idx[1]; idx[1] = idx[sh]; idx[sh] = tmp;

                plan.type[plan.n] = 3;
                plan.a[plan.n]    = (int)idx[0];
                plan.b[plan.n]    = (int)idx[1];
                plan.widx[plan.n] = 0;
                plan.n++;
            }
        }
    }
    return plan;
}

// ---------------------------------------------------------------------------
extern "C" void kernel_launch(void* const* d_in, const int* in_sizes, int n_in,
                              void* d_out, int out_size) {
    const float* x  = (const float*)d_in[0];
    const float* w1 = (const float*)d_in[1];
    const float* w2 = (const float*)d_in[2];
    float* out = (float*)d_out;

    Plan plan = make_plan_host();

    qconv_one_kernel<<<640, 256>>>(x, w1, w2, out, plan);
}

// round 9
// speedup vs baseline: 2.1641x; 2.1641x over previous
#include <cuda_runtime.h>
#include <cstdint>
#include <math.h>

// ---------------------------------------------------------------------------
//   x: [4,16,64,64,64] f32    weights1/2: [2,4] f32    out: [4,32,32,32,32] f32
// <Z0> = v^T S v  ->  81 coeffs in double-angle basis (1, cos2a, sin2a),
// 2a = min(pi, pi*y). Two kernels: tiny parallel build_W + main eval
// (2 adjacent l-points per thread to halve the W LDS broadcast cost).
// ---------------------------------------------------------------------------

#define MAXOPS 64

struct Plan {
    int n;
    int type[MAXOPS];   // 0=RX, 1=RY, 2=RZ, 3=CNOT
    int a[MAXOPS];      // rot wire, or cnot control
    int b[MAXOPS];      // cnot target
    int widx[MAXOPS];   // weights flat index l*4+i
};

__device__ float g_W[2][81];

// ---------------------------------------------------------------------------
// Prelude (verified R7): warp-shuffle circuit sim, bin, basis-change.
// grid = 2 blocks x 256 threads.
// ---------------------------------------------------------------------------
__global__ void build_W_kernel(const float* __restrict__ w1,
                               const float* __restrict__ w2,
                               Plan plan) {
    __shared__ float Ur[16][16], Ui[16][16];
    __shared__ float WA[81], WB[81];
    const float* w = (blockIdx.x == 0) ? w1 : w2;
    int t    = threadIdx.x;
    int col  = t >> 4;
    int amp  = t & 15;
    int lane = t & 31;

    float sr = (amp == col) ? 1.f : 0.f;
    float si = 0.f;

    for (int o = 0; o < plan.n; o++) {
        int ty = plan.type[o];
        if (ty == 3) {
            int bcb = 3 - plan.a[o], btb = 3 - plan.b[o];
            int src_amp  = amp ^ ((((amp >> bcb) & 1) ? 1 : 0) << btb);
            int src_lane = (lane & 16) | src_amp;
            sr = __shfl_sync(0xFFFFFFFFu, sr, src_lane);
            si = __shfl_sync(0xFFFFFFFFu, si, src_lane);
        } else {
            float th = w[plan.widx[o]];
            float c = cosf(0.5f * th), s = sinf(0.5f * th);
            float a00r = c, a00i = 0.f, a01r = 0.f, a01i = 0.f;
            float a10r = 0.f, a10i = 0.f, a11r = c, a11i = 0.f;
            if (ty == 0)      { a01i = -s; a10i = -s; }      // RX
            else if (ty == 1) { a01r = -s; a10r =  s; }      // RY
            else              { a00i = -s; a11i =  s; }      // RZ
            int bitp = 3 - plan.a[o];
            int str  = 1 << bitp;
            float pr = __shfl_xor_sync(0xFFFFFFFFu, sr, str);
            float pi = __shfl_xor_sync(0xFFFFFFFFu, si, str);
            int bit = (amp >> bitp) & 1;
            float xr = bit ? pr : sr, xi = bit ? pi : si;
            float yr = bit ? sr : pr, yi = bit ? si : pi;
            float r0r = bit ? a10r : a00r, r0i = bit ? a10i : a00i;
            float r1r = bit ? a11r : a01r, r1i = bit ? a11i : a01i;
            sr = r0r * xr - r0i * xi + r1r * yr - r1i * yi;
            si = r0r * xi + r0i * xr + r1r * yi + r1i * yr;
        }
    }
    Ur[amp][col] = sr;
    Ui[amp][col] = si;
    if (t < 81) WA[t] = 0.f;
    __syncthreads();

    {
        int r = t >> 4, c = t & 15;
        float acc = 0.f;
        #pragma unroll
        for (int k = 0; k < 16; k++) {
            float z = (k & 8) ? -1.f : 1.f;
            acc += z * (Ur[k][r] * Ur[k][c] + Ui[k][r] * Ui[k][c]);
        }
        int m0 = ((r >> 3) & 1) + ((c >> 3) & 1);
        int m1 = ((r >> 2) & 1) + ((c >> 2) & 1);
        int m2 = ((r >> 1) & 1) + ((c >> 1) & 1);
        int m3 = (r & 1) + (c & 1);
        atomicAdd(&WA[((m0 * 3 + m1) * 3 + m2) * 3 + m3], acc);
    }

    #define XFORM(SRC, DST, S)                                            \
        __syncthreads();                                                  \
        if (t < 81) {                                                     \
            int n = (t / (S)) % 3;                                        \
            int base = t - n * (S);                                       \
            float i0 = SRC[base], i1 = SRC[base + (S)], i2 = SRC[base + 2 * (S)]; \
            DST[t] = (n == 0) ? 0.5f * (i0 + i2)                          \
                   : (n == 1) ? 0.5f * (i0 - i2) : 0.5f * i1;             \
        }
    XFORM(WA, WB, 27)
    XFORM(WB, WA, 9)
    XFORM(WA, WB, 3)
    XFORM(WB, WA, 1)
    #undef XFORM

    __syncthreads();
    if (t < 81) g_W[blockIdx.x][t] = WA[t];
}

// ---------------------------------------------------------------------------
// Main kernel. grid = 640 blocks x 256 threads:
//   [0,512):   compute. blk = bc*8 + jg;  thread = slice(1b) k(4b) lq(3b);
//              j = 2*jg+slice, each thread does points (k, 2lq) and (k, 2lq+1)
//   [512,640): zero-fill of the j>=16 half (one (b,ch) 64KB chunk per block)
// ---------------------------------------------------------------------------
__global__ void __launch_bounds__(256)
qconv_main_kernel(const float* __restrict__ x, float* __restrict__ out) {
    int t = threadIdx.x;

    if (blockIdx.x >= 512) {
        int zi = blockIdx.x - 512;           // 0..127 -> (b, ch)
        float4* dst = reinterpret_cast<float4*>(
            out + (size_t)(zi >> 5) * 1048576 + (size_t)(zi & 31) * 32768 + 16384);
        const float4 z4 = make_float4(0.f, 0.f, 0.f, 0.f);
        #pragma unroll
        for (int r = 0; r < 16; r++) dst[t + 256 * r] = z4;
        return;
    }

    __shared__ float Wsh[2][81];
    __shared__ __align__(16) float tile[2][2][16][16];   // [set][slice][k][l]

    if (t < 162) ((float*)Wsh)[t] = ((const float*)g_W)[t];

    int bc    = blockIdx.x >> 3;   // b*16 + c
    int jg    = blockIdx.x & 7;
    int slice = t >> 7;            // 0..1
    int k     = (t >> 3) & 15;
    int lq    = t & 7;
    int j     = 2 * jg + slice;

    const float* xb = x + (size_t)bc * 262144 + (size_t)(2 * j) * 4096
                        + (size_t)(2 * k) * 64 + 4 * lq;
    float4 v00 = *reinterpret_cast<const float4*>(xb);
    float4 v01 = *reinterpret_cast<const float4*>(xb + 64);
    float4 v10 = *reinterpret_cast<const float4*>(xb + 4096);
    float4 v11 = *reinterpret_cast<const float4*>(xb + 4096 + 64);

    // per-point trig: CC/SS[p][dj][dk][dl], p = l parity
    const float PI_F = 3.14159265358979323846f;
    float CC[2][2][2][2], SS[2][2][2][2];
    {
        const float4* vv[2][2] = { { &v00, &v01 }, { &v10, &v11 } };
        #pragma unroll
        for (int dj = 0; dj < 2; dj++)
            #pragma unroll
            for (int dk = 0; dk < 2; dk++) {
                float4 v = *vv[dj][dk];
                float g[2][2] = { { v.x, v.y }, { v.z, v.w } };  // [p][dl]
                #pragma unroll
                for (int p = 0; p < 2; p++)
                    #pragma unroll
                    for (int dl = 0; dl < 2; dl++) {
                        float th2 = fminf(PI_F, PI_F * g[p][dl]);
                        __sincosf(th2, &SS[p][dj][dk][dl], &CC[p][dj][dk][dl]);
                    }
            }
    }

    __syncthreads();   // Wsh ready

    #define MONO(M, Ca, Sa, Cb, Sb)                                           \
        { M[0] = 1.f;  M[1] = (Cb); M[2] = (Sb);                              \
          M[3] = (Ca); M[4] = (Ca) * (Cb); M[5] = (Ca) * (Sb);                \
          M[6] = (Sa); M[7] = (Sa) * (Cb); M[8] = (Sa) * (Sb); }

    float e[2][2];   // [set][p]
    #pragma unroll
    for (int s = 0; s < 2; s++) {
        float M01[2][9], M23[2][9];
        #pragma unroll
        for (int p = 0; p < 2; p++) {
            if (s == 0) {
                // circuit 1: q = g(0,0,0), g(1,1,0), g(0,1,1), g(1,0,1)
                MONO(M01[p], CC[p][0][0][0], SS[p][0][0][0],
                             CC[p][1][1][0], SS[p][1][1][0]);
                MONO(M23[p], CC[p][0][1][1], SS[p][0][1][1],
                             CC[p][1][0][1], SS[p][1][0][1]);
            } else {
                // circuit 2: q = g(1,1,1), g(0,0,1), g(1,0,0), g(0,1,0)
                MONO(M01[p], CC[p][1][1][1], SS[p][1][1][1],
                             CC[p][0][0][1], SS[p][0][0][1]);
                MONO(M23[p], CC[p][1][0][0], SS[p][1][0][0],
                             CC[p][0][1][0], SS[p][0][1][0]);
            }
        }
        float e0 = 0.f, e1 = 0.f;
        #pragma unroll
        for (int a = 0; a < 9; a++) {
            float t0 = 0.f, t1 = 0.f;
            #pragma unroll
            for (int b = 0; b < 9; b++) {
                float wv = Wsh[s][a * 9 + b];      // one LDS serves 2 points
                t0 = fmaf(wv, M23[0][b], t0);
                t1 = fmaf(wv, M23[1][b], t1);
            }
            e0 = fmaf(M01[0][a], t0, e0);
            e1 = fmaf(M01[1][a], t1, e1);
        }
        e[s][0] = e0;
        e[s][1] = e1;
    }
    #undef MONO

    tile[0][slice][k][2 * lq]     = e[0][0];
    tile[0][slice][k][2 * lq + 1] = e[0][1];
    tile[1][slice][k][2 * lq]     = e[1][0];
    tile[1][slice][k][2 * lq + 1] = e[1][1];
    __syncthreads();

    // epilogue: 4 output slices (2 sets x 2 j), zero-padded to 32x32
    int b  = bc >> 4, c = bc & 15;
    int k2 = t >> 3;   // 0..31
    int q  = t & 7;    // float4 quad
    const float4 z4 = make_float4(0.f, 0.f, 0.f, 0.f);
    #pragma unroll
    for (int s = 0; s < 2; s++)
        #pragma unroll
        for (int js = 0; js < 2; js++) {
            float4 v = (k2 < 16 && q < 4)
                     ? reinterpret_cast<const float4*>(tile[s][js][k2])[q] : z4;
            float4* dst = reinterpret_cast<float4*>(
                out + (size_t)b * 1048576 + (size_t)(c + 16 * s) * 32768
                    + (size_t)(2 * jg + js) * 1024);
            dst[t] = v;
        }
}

// ---------------------------------------------------------------------------
// Host: exact numpy default_rng(1234) plan generation (verified R3).
// ---------------------------------------------------------------------------
typedef unsigned __int128 u128;

struct NpRng {
    u128 state, inc;
    bool has32;
    uint32_t buf32;

    static u128 mult() {
        return ((u128)2549297995355413924ULL << 64) | 4865540595714422341ULL;
    }
    uint64_t next64() {
        state = state * mult() + inc;
        uint64_t hi = (uint64_t)(state >> 64);
        uint64_t lo = (uint64_t)state;
        unsigned rot = (unsigned)(state >> 122);
        uint64_t v = hi ^ lo;
        return (v >> rot) | (v << ((64u - rot) & 63u));
    }
    uint32_t next32() {
        if (has32) { has32 = false; return buf32; }
        uint64_t n = next64();
        has32 = true;
        buf32 = (uint32_t)(n >> 32);
        return (uint32_t)n;
    }
    double nextDouble() {
        return (double)(next64() >> 11) * (1.0 / 9007199254740992.0);
    }
    uint32_t lemire32(uint32_t rng) {
        uint32_t rng_excl = rng + 1u;
        uint64_t m = (uint64_t)next32() * (uint64_t)rng_excl;
        uint32_t leftover = (uint32_t)m;
        if (leftover < rng_excl) {
            uint32_t threshold = (uint32_t)((0xFFFFFFFFu - rng) % rng_excl);
            while (leftover < threshold) {
                m = (uint64_t)next32() * (uint64_t)rng_excl;
                leftover = (uint32_t)m;
            }
        }
        return (uint32_t)(m >> 32);
    }
};

static Plan make_plan_host() {
    const uint32_t INIT_A = 0x43b0d7e5u, MULT_A = 0x931e8875u;
    const uint32_t INIT_B = 0x8b51f9ddu, MULT_B = 0x58f38dedu;
    const uint32_t MIX_L  = 0xca01f9ddu, MIX_R  = 0x4973f715u;

    uint32_t pool[4];
    uint32_t hc = INIT_A;
    auto hashmix = [&](uint32_t v) -> uint32_t {
        v ^= hc; hc *= MULT_A; v *= hc; v ^= v >> 16; return v;
    };
    auto mixf = [&](uint32_t x, uint32_t y) -> uint32_t {
        uint32_t r = x * MIX_L - y * MIX_R; r ^= r >> 16; return r;
    };
    pool[0] = hashmix(1234u);
    pool[1] = hashmix(0u);
    pool[2] = hashmix(0u);
    pool[3] = hashmix(0u);
    for (int s = 0; s < 4; s++)
        for (int d = 0; d < 4; d++)
            if (s != d) pool[d] = mixf(pool[d], hashmix(pool[s]));

    uint32_t hb = INIT_B;
    uint32_t st32[8];
    for (int i = 0; i < 8; i++) {
        uint32_t dv = pool[i & 3];
        dv ^= hb; hb *= MULT_B; dv *= hb; dv ^= dv >> 16;
        st32[i] = dv;
    }
    uint64_t s64[4];
    for (int i = 0; i < 4; i++)
        s64[i] = (uint64_t)st32[2 * i] | ((uint64_t)st32[2 * i + 1] << 32);

    NpRng rng;
    u128 initstate = ((u128)s64[0] << 64) | s64[1];
    u128 initseq   = ((u128)s64[2] << 64) | s64[3];
    rng.inc   = (initseq << 1) | 1;
    rng.state = 0;
    rng.state = rng.state * NpRng::mult() + rng.inc;
    rng.state += initstate;
    rng.state = rng.state * NpRng::mult() + rng.inc;
    rng.has32 = false;
    rng.buf32 = 0;

    Plan plan;
    plan.n = 0;
    for (int l = 0; l < 2; l++) {
        int i = 0;
        while (i < 4 && plan.n < MAXOPS) {
            if (rng.nextDouble() > 0.3) {
                int g = (int)rng.lemire32(2);
                int w = (int)rng.lemire32(3);
                plan.type[plan.n] = g;
                plan.a[plan.n]    = w;
                plan.b[plan.n]    = 0;
                plan.widx[plan.n] = l * 4 + i;
                plan.n++;
                i++;
            } else {
                uint64_t hash_set[4] = { ~0ULL, ~0ULL, ~0ULL, ~0ULL };
                int64_t idx[2];
                for (int jf = 2; jf <= 3; jf++) {
                    uint64_t val = (uint64_t)rng.lemire32((uint32_t)jf);
                    uint64_t loc = val & 3;
                    while (hash_set[loc] != ~0ULL && hash_set[loc] != val)
                        loc = (loc + 1) & 3;
                    if (hash_set[loc] == ~0ULL) {
                        hash_set[loc] = val;
                        idx[jf - 2] = (int64_t)val;
                    } else {
                        loc = (uint64_t)jf & 3;
                        while (hash_set[loc] != ~0ULL) loc = (loc + 1) & 3;
                        hash_set[loc] = (uint64_t)jf;
                        idx[jf - 2] = jf;
                    }
                }
                uint32_t sh = rng.lemire32(1u);   // Lemire-32 (top bit)
                int64_t tmp = idx[1]; idx[1] = idx[sh]; idx[sh] = tmp;

                plan.type[plan.n] = 3;
                plan.a[plan.n]    = (int)idx[0];
                plan.b[plan.n]    = (int)idx[1];
                plan.widx[plan.n] = 0;
                plan.n++;
            }
        }
    }
    return plan;
}

// ---------------------------------------------------------------------------
extern "C" void kernel_launch(void* const* d_in, const int* in_sizes, int n_in,
                              void* d_out, int out_size) {
    const float* x  = (const float*)d_in[0];
    const float* w1 = (const float*)d_in[1];
    const float* w2 = (const float*)d_in[2];
    float* out = (float*)d_out;

    Plan plan = make_plan_host();

    build_W_kernel<<<2, 256>>>(w1, w2, plan);
    qconv_main_kernel<<<640, 256>>>(x, out);
}